// round 8
// baseline (speedup 1.0000x reference)
#include <cuda_runtime.h>
#include <cuda_bf16.h>
#include <cstdint>

#define BB   4
#define SS   2048
#define DD   1024
#define HH   16
#define DKK  64
#define MROWS (BB*SS)   // 8192

// ---------------- scratch ----------------------------------------------------
__device__ __align__(128) __nv_bfloat16 g_qi[MROWS * DD];
__device__ __align__(128) __nv_bfloat16 g_ki[MROWS * DD];
__device__ __align__(128) __nv_bfloat16 g_vi[MROWS * DD];
__device__ __align__(128) __nv_bfloat16 g_wq[DD * DD];
__device__ __align__(128) __nv_bfloat16 g_wk[DD * DD];
__device__ __align__(128) __nv_bfloat16 g_wv[DD * DD];
__device__ __align__(128) __nv_bfloat16 g_wo[DD * DD];
__device__ __align__(128) __nv_bfloat16 g_qp[MROWS * DD];
__device__ __align__(128) __nv_bfloat16 g_kp[MROWS * DD];
__device__ __align__(128) __nv_bfloat16 g_vp[MROWS * DD];
__device__ __align__(128) __nv_bfloat16 g_ctx[MROWS * DD];
__device__ __align__(128) float g_x[MROWS * DD];

// ---------------- helpers ----------------------------------------------------
__device__ __forceinline__ unsigned packbf(float lo, float hi) {
    unsigned r;
    asm("cvt.rn.bf16x2.f32 %0, %1, %2;" : "=r"(r) : "f"(hi), "f"(lo));
    return r;
}
__device__ __forceinline__ void mma_bf16(float (&c)[4], const unsigned (&a)[4],
                                         unsigned b0, unsigned b1) {
    asm volatile(
        "mma.sync.aligned.m16n8k16.row.col.f32.bf16.bf16.f32 "
        "{%0,%1,%2,%3}, {%4,%5,%6,%7}, {%8,%9}, {%0,%1,%2,%3};\n"
        : "+f"(c[0]), "+f"(c[1]), "+f"(c[2]), "+f"(c[3])
        : "r"(a[0]), "r"(a[1]), "r"(a[2]), "r"(a[3]), "r"(b0), "r"(b1));
}
__device__ __forceinline__ void ldsm4(unsigned (&r)[4], unsigned addr) {
    asm volatile("ldmatrix.sync.aligned.m8n8.x4.shared.b16 {%0,%1,%2,%3}, [%4];"
                 : "=r"(r[0]), "=r"(r[1]), "=r"(r[2]), "=r"(r[3]) : "r"(addr));
}
__device__ __forceinline__ void ldsm4t(unsigned (&r)[4], unsigned addr) {
    asm volatile("ldmatrix.sync.aligned.m8n8.x4.trans.shared.b16 {%0,%1,%2,%3}, [%4];"
                 : "=r"(r[0]), "=r"(r[1]), "=r"(r[2]), "=r"(r[3]) : "r"(addr));
}
__device__ __forceinline__ void cpa16(unsigned s, const void* g) {
    asm volatile("cp.async.cg.shared.global [%0], [%1], 16;" :: "r"(s), "l"(g));
}
__device__ __forceinline__ void cp_commit() { asm volatile("cp.async.commit_group;"); }
template <int N>
__device__ __forceinline__ void cp_wait() { asm volatile("cp.async.wait_group %0;" :: "n"(N)); }

// ---------------- fp32 -> bf16 convert pass -----------------------------------
__global__ void __launch_bounds__(256) convert_kernel(
    const float* __restrict__ q, const float* __restrict__ k, const float* __restrict__ v,
    const float* __restrict__ Wq, const float* __restrict__ Wk,
    const float* __restrict__ Wv, const float* __restrict__ Wo) {
    const size_t Q4 = (size_t)MROWS * DD / 4;
    const size_t W4 = (size_t)DD * DD / 4;
    size_t i = (size_t)blockIdx.x * blockDim.x + threadIdx.x;
    const float* src;
    __nv_bfloat16* dst;
    size_t off;
    if (i < Q4)            { src = q;  dst = g_qi; off = i; }
    else if (i < 2 * Q4)   { src = k;  dst = g_ki; off = i - Q4; }
    else if (i < 3 * Q4)   { src = v;  dst = g_vi; off = i - 2 * Q4; }
    else {
        size_t w = i - 3 * Q4;
        size_t sel = w / W4;
        off = w - sel * W4;
        src = (sel == 0) ? Wq : (sel == 1) ? Wk : (sel == 2) ? Wv : Wo;
        dst = (sel == 0) ? g_wq : (sel == 1) ? g_wk : (sel == 2) ? g_wv : g_wo;
    }
    float4 xv = *reinterpret_cast<const float4*>(src + off * 4);
    uint2 p;
    p.x = packbf(xv.x, xv.y);
    p.y = packbf(xv.z, xv.w);
    *reinterpret_cast<uint2*>(dst + off * 4) = p;
}

// ---------------- GEMM: 128x128 tile, 4 warps, warp tile 64x64, 4-stage async -
#define GLD 40            // bf16 per smem row (80B stride, ldsm conflict-free)
#define GSTAGES 4
#define GSTG (128 * GLD * 2)             // bytes per stage per array (10240)
#define GEMM_SMEM (2 * GSTAGES * GSTG)   // 81920

template <bool OBF>
__device__ __forceinline__ void gemm_body(const __nv_bfloat16* __restrict__ A,
                                          const __nv_bfloat16* __restrict__ W,
                                          const float* __restrict__ bias,
                                          const float* __restrict__ R,
                                          void* Cv, int bx, int by, float oscale) {
    extern __shared__ __align__(16) char gsm[];
    const int tid = threadIdx.x;
    const int warp = tid >> 5, lane = tid & 31;
    const int g = lane >> 2, tg = lane & 3;
    const int wm = (warp >> 1) * 64;       // 2x2 warp grid, warp tile 64x64
    const int wn = (warp & 1) * 64;
    const int bm0 = bx * 128, bn0 = by * 128;
    const int lrow = lane & 15, lcol = (lane >> 4) << 3;

    const unsigned sA = (unsigned)__cvta_generic_to_shared(gsm);
    const unsigned sB = sA + GSTAGES * GSTG;

    const __nv_bfloat16* Ab = A + (size_t)bm0 * DD;
    const __nv_bfloat16* Wb = W + (size_t)bn0 * DD;

    auto loadT = [&](int kt, int st) {
        const __nv_bfloat16* ga = Ab + kt * 32;
        const __nv_bfloat16* gb = Wb + kt * 32;
#pragma unroll
        for (int j = 0; j < 4; j++) {
            cpa16(sA + st * GSTG + tid * 80 + j * 16, ga + (size_t)tid * DD + j * 8);
            cpa16(sB + st * GSTG + tid * 80 + j * 16, gb + (size_t)tid * DD + j * 8);
        }
    };

    const int NT = DD / 32;   // 32
    loadT(0, 0); cp_commit();
    loadT(1, 1); cp_commit();
    loadT(2, 2); cp_commit();

    float acc[4][8][4] = {};

    for (int kt = 0; kt < NT; kt++) {
        cp_wait<2>();
        __syncthreads();
        const int st = kt & 3;
        if (kt + 3 < NT) loadT(kt + 3, (kt + 3) & 3);
        cp_commit();
#pragma unroll
        for (int kc = 0; kc < 2; kc++) {
            unsigned a[4][4];
#pragma unroll
            for (int mf = 0; mf < 4; mf++)
                ldsm4(a[mf], sA + st * GSTG +
                              ((wm + mf * 16 + lrow) * GLD + kc * 16 + lcol) * 2);
            unsigned b[4][4];
#pragma unroll
            for (int p = 0; p < 4; p++)
                ldsm4(b[p], sB + st * GSTG +
                             ((wn + p * 16 + lrow) * GLD + kc * 16 + lcol) * 2);
#pragma unroll
            for (int mf = 0; mf < 4; mf++)
#pragma unroll
                for (int nf = 0; nf < 8; nf++)
                    mma_bf16(acc[mf][nf], a[mf], b[nf >> 1][nf & 1], b[nf >> 1][(nf & 1) + 2]);
        }
    }

    // epilogue
#pragma unroll
    for (int mf = 0; mf < 4; mf++) {
        int r0 = bm0 + wm + mf * 16 + g;
        int r1 = r0 + 8;
#pragma unroll
        for (int nf = 0; nf < 8; nf++) {
            int cc = bn0 + wn + nf * 8 + 2 * tg;
            float b0 = bias[cc], b1 = bias[cc + 1];
            float v00 = (acc[mf][nf][0] + b0) * oscale;
            float v01 = (acc[mf][nf][1] + b1) * oscale;
            float v10 = (acc[mf][nf][2] + b0) * oscale;
            float v11 = (acc[mf][nf][3] + b1) * oscale;
            if (OBF) {
                __nv_bfloat16* Cb = (__nv_bfloat16*)Cv;
                *reinterpret_cast<unsigned*>(Cb + (size_t)r0 * DD + cc) = packbf(v00, v01);
                *reinterpret_cast<unsigned*>(Cb + (size_t)r1 * DD + cc) = packbf(v10, v11);
            } else {
                float* Cf = (float*)Cv;
                float2 q0 = *reinterpret_cast<const float2*>(R + (size_t)r0 * DD + cc);
                float2 q1 = *reinterpret_cast<const float2*>(R + (size_t)r1 * DD + cc);
                v00 += q0.x; v01 += q0.y; v10 += q1.x; v11 += q1.y;
                *reinterpret_cast<float2*>(Cf + (size_t)r0 * DD + cc) = make_float2(v00, v01);
                *reinterpret_cast<float2*>(Cf + (size_t)r1 * DD + cc) = make_float2(v10, v11);
            }
        }
    }
}

__global__ void __launch_bounds__(128) qkv_kernel(const float* __restrict__ bq,
                                                  const float* __restrict__ bk,
                                                  const float* __restrict__ bv) {
    int z = blockIdx.z;
    const __nv_bfloat16* A = (z == 0) ? g_qi : (z == 1) ? g_ki : g_vi;
    const __nv_bfloat16* W = (z == 0) ? g_wq : (z == 1) ? g_wk : g_wv;
    const float* bias = (z == 0) ? bq : (z == 1) ? bk : bv;
    __nv_bfloat16* C = (z == 0) ? g_qp : (z == 1) ? g_kp : g_vp;
    // fold softmax 1/sqrt(dk) into the Q projection
    float oscale = (z == 0) ? 0.125f : 1.0f;
    gemm_body<true>(A, W, bias, nullptr, C, blockIdx.x, blockIdx.y, oscale);
}

__global__ void __launch_bounds__(128) oproj_kernel(const float* __restrict__ q,
                                                    const float* __restrict__ bo) {
    gemm_body<false>(g_ctx, g_wo, bo, q, g_x, blockIdx.x, blockIdx.y, 1.0f);
}

// ---------------- Flash attention (bf16, cp.async, Q-tile 256, Q-frag hoist) -
#define BQ 256
#define BKV 64
#define LDS 72
#define ATT_SMEM_BYTES ((BQ + 2 * BKV + 2 * BKV) * LDS * 2)   // 73728

__global__ void __launch_bounds__(256, 1) attn_kernel() {
    extern __shared__ __align__(16) __nv_bfloat16 sm[];
    __nv_bfloat16* Qs = sm;
    __nv_bfloat16* Ks = sm + BQ * LDS;
    __nv_bfloat16* Vs = sm + BQ * LDS + 2 * BKV * LDS;

    const int bh = blockIdx.y;
    const int qt = blockIdx.x;
    const __nv_bfloat16* qb = g_qp + (size_t)bh * SS * DKK;
    const __nv_bfloat16* kb = g_kp + (size_t)bh * SS * DKK;
    const __nv_bfloat16* vb = g_vp + (size_t)bh * SS * DKK;
    __nv_bfloat16* ob = g_ctx + (size_t)bh * SS * DKK;

    const int tid = threadIdx.x;
    const int warp = tid >> 5, lane = tid & 31;
    const int g = lane >> 2, tg = lane & 3;
    const int lrow = lane & 15, lcol = (lane >> 4) << 3;
    const int rr = warp * 32;

    const unsigned sQ = (unsigned)__cvta_generic_to_shared(Qs);
    const unsigned sK = (unsigned)__cvta_generic_to_shared(Ks);
    const unsigned sV = (unsigned)__cvta_generic_to_shared(Vs);
    const unsigned KVSZ = BKV * LDS * 2;

    auto loadKV = [&](int kt, int buf) {
#pragma unroll
        for (int i = 0; i < 2; i++) {
            int id = tid + i * 256;
            int r = id >> 3, c8 = id & 7;
            cpa16(sK + buf * KVSZ + (r * LDS + c8 * 8) * 2,
                  kb + (size_t)(kt * BKV + r) * DKK + c8 * 8);
            cpa16(sV + buf * KVSZ + (r * LDS + c8 * 8) * 2,
                  vb + (size_t)(kt * BKV + r) * DKK + c8 * 8);
        }
    };

#pragma unroll
    for (int i = 0; i < 8; i++) {
        int id = tid + i * 256;
        int r = id >> 3, c8 = id & 7;
        cpa16(sQ + (r * LDS + c8 * 8) * 2,
              qb + (size_t)(qt * BQ + r) * DKK + c8 * 8);
    }
    loadKV(0, 0);
    cp_commit();
    loadKV(1, 1);
    cp_commit();

    // hoist Q fragments (loop-invariant; Q is pre-scaled by 1/sqrt(dk))
    cp_wait<1>();
    __syncthreads();
    unsigned qa[2][4][4];
#pragma unroll
    for (int mf = 0; mf < 2; mf++)
#pragma unroll
        for (int kc = 0; kc < 4; kc++)
            ldsm4(qa[mf][kc], sQ + ((rr + mf * 16 + lrow) * LDS + kc * 16 + lcol) * 2);

    float o[2][8][4] = {};
    float rmax[4] = {-1e30f, -1e30f, -1e30f, -1e30f};
    float rsum[4] = {};

    const int NT = SS / BKV;
    for (int kt = 0; kt < NT; kt++) {
        cp_wait<1>();
        __syncthreads();
        const int cur = kt & 1;

        float s[2][8][4] = {};
#pragma unroll
        for (int kc = 0; kc < 4; kc++) {
            unsigned kf[4][4];
#pragma unroll
            for (int p = 0; p < 4; p++)
                ldsm4(kf[p], sK + cur * KVSZ + ((p * 16 + lrow) * LDS + kc * 16 + lcol) * 2);
#pragma unroll
            for (int mf = 0; mf < 2; mf++)
#pragma unroll
                for (int nf = 0; nf < 8; nf++)
                    mma_bf16(s[mf][nf], qa[mf][kc], kf[nf >> 1][nf & 1], kf[nf >> 1][(nf & 1) + 2]);
        }

        float mloc[4] = {-1e30f, -1e30f, -1e30f, -1e30f};
#pragma unroll
        for (int mf = 0; mf < 2; mf++)
#pragma unroll
            for (int nf = 0; nf < 8; nf++) {
                mloc[mf * 2 + 0] = fmaxf(mloc[mf * 2 + 0], fmaxf(s[mf][nf][0], s[mf][nf][1]));
                mloc[mf * 2 + 1] = fmaxf(mloc[mf * 2 + 1], fmaxf(s[mf][nf][2], s[mf][nf][3]));
            }
        float al[4];
#pragma unroll
        for (int j = 0; j < 4; j++) {
            mloc[j] = fmaxf(mloc[j], __shfl_xor_sync(0xffffffffu, mloc[j], 1));
            mloc[j] = fmaxf(mloc[j], __shfl_xor_sync(0xffffffffu, mloc[j], 2));
            float nm = fmaxf(rmax[j], mloc[j]);
            al[j] = __expf(rmax[j] - nm);
            rmax[j] = nm;
        }
        float l[4] = {};
        unsigned pa[2][4][4];
#pragma unroll
        for (int mf = 0; mf < 2; mf++)
#pragma unroll
            for (int nf = 0; nf < 8; nf++) {
                float p0 = __expf(s[mf][nf][0] - rmax[mf * 2 + 0]);
                float p1 = __expf(s[mf][nf][1] - rmax[mf * 2 + 0]);
                float p2 = __expf(s[mf][nf][2] - rmax[mf * 2 + 1]);
                float p3 = __expf(s[mf][nf][3] - rmax[mf * 2 + 1]);
                l[mf * 2 + 0] += p0 + p1;
                l[mf * 2 + 1] += p2 + p3;
                int kc = nf >> 1, off = (nf & 1) * 2;
                pa[mf][kc][off + 0] = packbf(p0, p1);
                pa[mf][kc][off + 1] = packbf(p2, p3);
            }
#pragma unroll
        for (int j = 0; j < 4; j++) {
            l[j] += __shfl_xor_sync(0xffffffffu, l[j], 1);
            l[j] += __shfl_xor_sync(0xffffffffu, l[j], 2);
            rsum[j] = rsum[j] * al[j] + l[j];
        }
#pragma unroll
        for (int mf = 0; mf < 2; mf++)
#pragma unroll
            for (int nf = 0; nf < 8; nf++) {
                o[mf][nf][0] *= al[mf * 2 + 0]; o[mf][nf][1] *= al[mf * 2 + 0];
                o[mf][nf][2] *= al[mf * 2 + 1]; o[mf][nf][3] *= al[mf * 2 + 1];
            }

#pragma unroll
        for (int kc = 0; kc < 4; kc++) {
            unsigned vf[4][4];
#pragma unroll
            for (int p = 0; p < 4; p++)
                ldsm4t(vf[p], sV + cur * KVSZ + ((kc * 16 + lrow) * LDS + p * 16 + lcol) * 2);
#pragma unroll
            for (int mf = 0; mf < 2; mf++)
#pragma unroll
                for (int nf = 0; nf < 8; nf++)
                    mma_bf16(o[mf][nf], pa[mf][kc],
                             vf[nf >> 1][(nf & 1) * 2], vf[nf >> 1][(nf & 1) * 2 + 1]);
        }

        __syncthreads();
        if (kt + 2 < NT) loadKV(kt + 2, cur);
        cp_commit();
    }

    float inv[4];
#pragma unroll
    for (int j = 0; j < 4; j++) inv[j] = 1.f / rsum[j];
#pragma unroll
    for (int mf = 0; mf < 2; mf++) {
        int row0 = qt * BQ + rr + mf * 16 + g;
        int row1 = row0 + 8;
#pragma unroll
        for (int nf = 0; nf < 8; nf++) {
            int cc = nf * 8 + 2 * tg;
            *reinterpret_cast<unsigned*>(ob + (size_t)row0 * DKK + cc) =
                packbf(o[mf][nf][0] * inv[mf * 2 + 0], o[mf][nf][1] * inv[mf * 2 + 0]);
            *reinterpret_cast<unsigned*>(ob + (size_t)row1 * DKK + cc) =
                packbf(o[mf][nf][2] * inv[mf * 2 + 1], o[mf][nf][3] * inv[mf * 2 + 1]);
        }
    }
}

// ---------------- LayerNorm ---------------------------------------------------
__global__ void __launch_bounds__(256) ln_kernel(const float* __restrict__ gamma,
                                                 const float* __restrict__ beta,
                                                 float* __restrict__ out) {
    __shared__ float red[16];
    const int row = blockIdx.x;
    const int tid = threadIdx.x;
    const float* xr = g_x + (size_t)row * DD;
    float4 xv = *reinterpret_cast<const float4*>(xr + tid * 4);
    float s = xv.x + xv.y + xv.z + xv.w;
    float q2 = xv.x * xv.x + xv.y * xv.y + xv.z * xv.z + xv.w * xv.w;
#pragma unroll
    for (int off = 16; off > 0; off >>= 1) {
        s += __shfl_xor_sync(0xffffffffu, s, off);
        q2 += __shfl_xor_sync(0xffffffffu, q2, off);
    }
    int warp = tid >> 5, lane = tid & 31;
    if (lane == 0) { red[warp] = s; red[8 + warp] = q2; }
    __syncthreads();
    if (tid < 32) {
        float ss = (tid < 8) ? red[tid] : 0.f;
        float qq = (tid < 8) ? red[8 + tid] : 0.f;
#pragma unroll
        for (int off = 4; off > 0; off >>= 1) {
            ss += __shfl_xor_sync(0xffffffffu, ss, off);
            qq += __shfl_xor_sync(0xffffffffu, qq, off);
        }
        if (tid == 0) { red[0] = ss; red[1] = qq; }
    }
    __syncthreads();
    float mean = red[0] * (1.f / (float)DD);
    float var = red[1] * (1.f / (float)DD) - mean * mean;
    float inv = rsqrtf(var + 1e-6f);
    int c = tid * 4;
    float4 gv = *reinterpret_cast<const float4*>(gamma + c);
    float4 bv = *reinterpret_cast<const float4*>(beta + c);
    float4 ov;
    ov.x = (xv.x - mean) * inv * gv.x + bv.x;
    ov.y = (xv.y - mean) * inv * gv.y + bv.y;
    ov.z = (xv.z - mean) * inv * gv.z + bv.z;
    ov.w = (xv.w - mean) * inv * gv.w + bv.w;
    *reinterpret_cast<float4*>(out + (size_t)row * DD + c) = ov;
}

// ---------------- launch ------------------------------------------------------
extern "C" void kernel_launch(void* const* d_in, const int* in_sizes, int n_in,
                              void* d_out, int out_size) {
    const float* q     = (const float*)d_in[0];
    const float* k     = (const float*)d_in[1];
    const float* v     = (const float*)d_in[2];
    const float* Wq    = (const float*)d_in[3];
    const float* bq    = (const float*)d_in[4];
    const float* Wk    = (const float*)d_in[5];
    const float* bk    = (const float*)d_in[6];
    const float* Wv    = (const float*)d_in[7];
    const float* bv    = (const float*)d_in[8];
    const float* Wo    = (const float*)d_in[9];
    const float* bo    = (const float*)d_in[10];
    const float* gamma = (const float*)d_in[11];
    const float* beta  = (const float*)d_in[12];
    float* out = (float*)d_out;

    cudaFuncSetAttribute(attn_kernel, cudaFuncAttributeMaxDynamicSharedMemorySize,
                         ATT_SMEM_BYTES);
    cudaFuncSetAttribute(qkv_kernel, cudaFuncAttributeMaxDynamicSharedMemorySize,
                         GEMM_SMEM);
    cudaFuncSetAttribute(oproj_kernel, cudaFuncAttributeMaxDynamicSharedMemorySize,
                         GEMM_SMEM);

    convert_kernel<<<28672, 256>>>(q, k, v, Wq, Wk, Wv, Wo);
    qkv_kernel<<<dim3(64, 8, 3), 128, GEMM_SMEM>>>(bq, bk, bv);
    attn_kernel<<<dim3(SS / BQ, BB * HH), 256, ATT_SMEM_BYTES>>>();
    oproj_kernel<<<dim3(64, 8), 128, GEMM_SMEM>>>(q, bo);
    ln_kernel<<<MROWS, 256>>>(gamma, beta, out);
}

// round 9
// speedup vs baseline: 1.2664x; 1.2664x over previous
#include <cuda_runtime.h>
#include <cuda_bf16.h>
#include <cstdint>

#define BB   4
#define SS   2048
#define DD   1024
#define HH   16
#define DKK  64
#define MROWS (BB*SS)   // 8192

// ---------------- scratch ----------------------------------------------------
__device__ __align__(128) __nv_bfloat16 g_qi[MROWS * DD];
__device__ __align__(128) __nv_bfloat16 g_ki[MROWS * DD];
__device__ __align__(128) __nv_bfloat16 g_vi[MROWS * DD];
__device__ __align__(128) __nv_bfloat16 g_wq[DD * DD];
__device__ __align__(128) __nv_bfloat16 g_wk[DD * DD];
__device__ __align__(128) __nv_bfloat16 g_wv[DD * DD];
__device__ __align__(128) __nv_bfloat16 g_wo[DD * DD];
__device__ __align__(128) __nv_bfloat16 g_qp[MROWS * DD];
__device__ __align__(128) __nv_bfloat16 g_kp[MROWS * DD];
__device__ __align__(128) __nv_bfloat16 g_vp[MROWS * DD];
__device__ __align__(128) __nv_bfloat16 g_ctx[MROWS * DD];
__device__ __align__(128) float g_x[MROWS * DD];

// ---------------- helpers ----------------------------------------------------
__device__ __forceinline__ unsigned packbf(float lo, float hi) {
    unsigned r;
    asm("cvt.rn.bf16x2.f32 %0, %1, %2;" : "=r"(r) : "f"(hi), "f"(lo));
    return r;
}
__device__ __forceinline__ void mma_bf16(float (&c)[4], const unsigned (&a)[4],
                                         unsigned b0, unsigned b1) {
    asm volatile(
        "mma.sync.aligned.m16n8k16.row.col.f32.bf16.bf16.f32 "
        "{%0,%1,%2,%3}, {%4,%5,%6,%7}, {%8,%9}, {%0,%1,%2,%3};\n"
        : "+f"(c[0]), "+f"(c[1]), "+f"(c[2]), "+f"(c[3])
        : "r"(a[0]), "r"(a[1]), "r"(a[2]), "r"(a[3]), "r"(b0), "r"(b1));
}
__device__ __forceinline__ void ldsm4(unsigned (&r)[4], unsigned addr) {
    asm volatile("ldmatrix.sync.aligned.m8n8.x4.shared.b16 {%0,%1,%2,%3}, [%4];"
                 : "=r"(r[0]), "=r"(r[1]), "=r"(r[2]), "=r"(r[3]) : "r"(addr));
}
__device__ __forceinline__ void ldsm4t(unsigned (&r)[4], unsigned addr) {
    asm volatile("ldmatrix.sync.aligned.m8n8.x4.trans.shared.b16 {%0,%1,%2,%3}, [%4];"
                 : "=r"(r[0]), "=r"(r[1]), "=r"(r[2]), "=r"(r[3]) : "r"(addr));
}
__device__ __forceinline__ void cpa16(unsigned s, const void* g) {
    asm volatile("cp.async.cg.shared.global [%0], [%1], 16;" :: "r"(s), "l"(g));
}
__device__ __forceinline__ void cp_commit() { asm volatile("cp.async.commit_group;"); }
template <int N>
__device__ __forceinline__ void cp_wait() { asm volatile("cp.async.wait_group %0;" :: "n"(N)); }

// ---------------- fp32 -> bf16 convert pass -----------------------------------
__global__ void __launch_bounds__(256) convert_kernel(
    const float* __restrict__ q, const float* __restrict__ k, const float* __restrict__ v,
    const float* __restrict__ Wq, const float* __restrict__ Wk,
    const float* __restrict__ Wv, const float* __restrict__ Wo) {
    const size_t Q4 = (size_t)MROWS * DD / 4;
    const size_t W4 = (size_t)DD * DD / 4;
    size_t i = (size_t)blockIdx.x * blockDim.x + threadIdx.x;
    const float* src;
    __nv_bfloat16* dst;
    size_t off;
    if (i < Q4)            { src = q;  dst = g_qi; off = i; }
    else if (i < 2 * Q4)   { src = k;  dst = g_ki; off = i - Q4; }
    else if (i < 3 * Q4)   { src = v;  dst = g_vi; off = i - 2 * Q4; }
    else {
        size_t w = i - 3 * Q4;
        size_t sel = w / W4;
        off = w - sel * W4;
        src = (sel == 0) ? Wq : (sel == 1) ? Wk : (sel == 2) ? Wv : Wo;
        dst = (sel == 0) ? g_wq : (sel == 1) ? g_wk : (sel == 2) ? g_wv : g_wo;
    }
    float4 xv = *reinterpret_cast<const float4*>(src + off * 4);
    uint2 p;
    p.x = packbf(xv.x, xv.y);
    p.y = packbf(xv.z, xv.w);
    *reinterpret_cast<uint2*>(dst + off * 4) = p;
}

// -------- GEMM: 128x128 tile, 8 warps (2x4, warp 64x32), BK=64, 3-stage async -
#define GLD2 72                            // bf16 per smem row (144B stride)
#define GSTG2 (128 * GLD2 * 2)             // 18432 bytes per stage per matrix
#define GEMM_SMEM (2 * 3 * GSTG2)          // 110592

template <bool OBF>
__device__ __forceinline__ void gemm_body(const __nv_bfloat16* __restrict__ A,
                                          const __nv_bfloat16* __restrict__ W,
                                          const float* __restrict__ bias,
                                          const float* __restrict__ R,
                                          void* Cv, int bx, int by, float oscale) {
    extern __shared__ __align__(16) char gsm[];
    const int tid = threadIdx.x;
    const int warp = tid >> 5, lane = tid & 31;
    const int g = lane >> 2, tg = lane & 3;
    const int wm = (warp >> 2) * 64;       // 2x4 warp grid, warp tile 64x32
    const int wn = (warp & 3) * 32;
    const int bm0 = bx * 128, bn0 = by * 128;
    const int lrow = lane & 15, lcol = (lane >> 4) << 3;

    const unsigned sA = (unsigned)__cvta_generic_to_shared(gsm);
    const unsigned sB = sA + 3 * GSTG2;

    const __nv_bfloat16* Ab = A + (size_t)bm0 * DD;
    const __nv_bfloat16* Wb = W + (size_t)bn0 * DD;

    // one BK=64 stage: 128 rows x 64 cols x 2B = 16KB/matrix = 1024 x 16B chunks
    auto loadT = [&](int kt, int st) {
        const __nv_bfloat16* ga = Ab + kt * 64;
        const __nv_bfloat16* gb = Wb + kt * 64;
#pragma unroll
        for (int j = 0; j < 4; j++) {
            int id = tid + j * 256;
            int r = id >> 3, c8 = id & 7;
            cpa16(sA + st * GSTG2 + r * 144 + c8 * 16, ga + (size_t)r * DD + c8 * 8);
            cpa16(sB + st * GSTG2 + r * 144 + c8 * 16, gb + (size_t)r * DD + c8 * 8);
        }
    };

    const int NT = DD / 64;   // 16
    loadT(0, 0); cp_commit();
    loadT(1, 1); cp_commit();

    float acc[4][4][4] = {};

    for (int kt = 0; kt < NT; kt++) {
        cp_wait<1>();
        __syncthreads();
        const int st = kt % 3;
        if (kt + 2 < NT) loadT(kt + 2, (kt + 2) % 3);
        cp_commit();
#pragma unroll
        for (int kc = 0; kc < 4; kc++) {
            unsigned a[4][4];
#pragma unroll
            for (int mf = 0; mf < 4; mf++)
                ldsm4(a[mf], sA + st * GSTG2 +
                              ((wm + mf * 16 + lrow) * GLD2 + kc * 16 + lcol) * 2);
            unsigned b[2][4];
#pragma unroll
            for (int p = 0; p < 2; p++)
                ldsm4(b[p], sB + st * GSTG2 +
                             ((wn + p * 16 + lrow) * GLD2 + kc * 16 + lcol) * 2);
#pragma unroll
            for (int mf = 0; mf < 4; mf++)
#pragma unroll
                for (int nf = 0; nf < 4; nf++)
                    mma_bf16(acc[mf][nf], a[mf], b[nf >> 1][nf & 1], b[nf >> 1][(nf & 1) + 2]);
        }
    }

    // epilogue
#pragma unroll
    for (int mf = 0; mf < 4; mf++) {
        int r0 = bm0 + wm + mf * 16 + g;
        int r1 = r0 + 8;
#pragma unroll
        for (int nf = 0; nf < 4; nf++) {
            int cc = bn0 + wn + nf * 8 + 2 * tg;
            float b0 = bias[cc], b1 = bias[cc + 1];
            float v00 = (acc[mf][nf][0] + b0) * oscale;
            float v01 = (acc[mf][nf][1] + b1) * oscale;
            float v10 = (acc[mf][nf][2] + b0) * oscale;
            float v11 = (acc[mf][nf][3] + b1) * oscale;
            if (OBF) {
                __nv_bfloat16* Cb = (__nv_bfloat16*)Cv;
                *reinterpret_cast<unsigned*>(Cb + (size_t)r0 * DD + cc) = packbf(v00, v01);
                *reinterpret_cast<unsigned*>(Cb + (size_t)r1 * DD + cc) = packbf(v10, v11);
            } else {
                float* Cf = (float*)Cv;
                float2 q0 = *reinterpret_cast<const float2*>(R + (size_t)r0 * DD + cc);
                float2 q1 = *reinterpret_cast<const float2*>(R + (size_t)r1 * DD + cc);
                v00 += q0.x; v01 += q0.y; v10 += q1.x; v11 += q1.y;
                *reinterpret_cast<float2*>(Cf + (size_t)r0 * DD + cc) = make_float2(v00, v01);
                *reinterpret_cast<float2*>(Cf + (size_t)r1 * DD + cc) = make_float2(v10, v11);
            }
        }
    }
}

__global__ void __launch_bounds__(256, 2) qkv_kernel(const float* __restrict__ bq,
                                                     const float* __restrict__ bk,
                                                     const float* __restrict__ bv) {
    int z = blockIdx.z;
    const __nv_bfloat16* A = (z == 0) ? g_qi : (z == 1) ? g_ki : g_vi;
    const __nv_bfloat16* W = (z == 0) ? g_wq : (z == 1) ? g_wk : g_wv;
    const float* bias = (z == 0) ? bq : (z == 1) ? bk : bv;
    __nv_bfloat16* C = (z == 0) ? g_qp : (z == 1) ? g_kp : g_vp;
    // fold softmax 1/sqrt(dk) into the Q projection
    float oscale = (z == 0) ? 0.125f : 1.0f;
    gemm_body<true>(A, W, bias, nullptr, C, blockIdx.x, blockIdx.y, oscale);
}

__global__ void __launch_bounds__(256, 2) oproj_kernel(const float* __restrict__ q,
                                                       const float* __restrict__ bo) {
    gemm_body<false>(g_ctx, g_wo, bo, q, g_x, blockIdx.x, blockIdx.y, 1.0f);
}

// ---------------- Flash attention (bf16, cp.async, Q-tile 256, Q-frag hoist) -
#define BQ 256
#define BKV 64
#define LDS 72
#define ATT_SMEM_BYTES ((BQ + 2 * BKV + 2 * BKV) * LDS * 2)   // 73728

__global__ void __launch_bounds__(256, 1) attn_kernel() {
    extern __shared__ __align__(16) __nv_bfloat16 sm[];
    __nv_bfloat16* Qs = sm;
    __nv_bfloat16* Ks = sm + BQ * LDS;
    __nv_bfloat16* Vs = sm + BQ * LDS + 2 * BKV * LDS;

    const int bh = blockIdx.y;
    const int qt = blockIdx.x;
    const __nv_bfloat16* qb = g_qp + (size_t)bh * SS * DKK;
    const __nv_bfloat16* kb = g_kp + (size_t)bh * SS * DKK;
    const __nv_bfloat16* vb = g_vp + (size_t)bh * SS * DKK;
    __nv_bfloat16* ob = g_ctx + (size_t)bh * SS * DKK;

    const int tid = threadIdx.x;
    const int warp = tid >> 5, lane = tid & 31;
    const int g = lane >> 2, tg = lane & 3;
    const int lrow = lane & 15, lcol = (lane >> 4) << 3;
    const int rr = warp * 32;

    const unsigned sQ = (unsigned)__cvta_generic_to_shared(Qs);
    const unsigned sK = (unsigned)__cvta_generic_to_shared(Ks);
    const unsigned sV = (unsigned)__cvta_generic_to_shared(Vs);
    const unsigned KVSZ = BKV * LDS * 2;

    auto loadKV = [&](int kt, int buf) {
#pragma unroll
        for (int i = 0; i < 2; i++) {
            int id = tid + i * 256;
            int r = id >> 3, c8 = id & 7;
            cpa16(sK + buf * KVSZ + (r * LDS + c8 * 8) * 2,
                  kb + (size_t)(kt * BKV + r) * DKK + c8 * 8);
            cpa16(sV + buf * KVSZ + (r * LDS + c8 * 8) * 2,
                  vb + (size_t)(kt * BKV + r) * DKK + c8 * 8);
        }
    };

#pragma unroll
    for (int i = 0; i < 8; i++) {
        int id = tid + i * 256;
        int r = id >> 3, c8 = id & 7;
        cpa16(sQ + (r * LDS + c8 * 8) * 2,
              qb + (size_t)(qt * BQ + r) * DKK + c8 * 8);
    }
    loadKV(0, 0);
    cp_commit();
    loadKV(1, 1);
    cp_commit();

    // hoist Q fragments (loop-invariant; Q is pre-scaled by 1/sqrt(dk))
    cp_wait<1>();
    __syncthreads();
    unsigned qa[2][4][4];
#pragma unroll
    for (int mf = 0; mf < 2; mf++)
#pragma unroll
        for (int kc = 0; kc < 4; kc++)
            ldsm4(qa[mf][kc], sQ + ((rr + mf * 16 + lrow) * LDS + kc * 16 + lcol) * 2);

    float o[2][8][4] = {};
    float rmax[4] = {-1e30f, -1e30f, -1e30f, -1e30f};
    float rsum[4] = {};

    const int NT = SS / BKV;
    for (int kt = 0; kt < NT; kt++) {
        cp_wait<1>();
        __syncthreads();
        const int cur = kt & 1;

        float s[2][8][4] = {};
#pragma unroll
        for (int kc = 0; kc < 4; kc++) {
            unsigned kf[4][4];
#pragma unroll
            for (int p = 0; p < 4; p++)
                ldsm4(kf[p], sK + cur * KVSZ + ((p * 16 + lrow) * LDS + kc * 16 + lcol) * 2);
#pragma unroll
            for (int mf = 0; mf < 2; mf++)
#pragma unroll
                for (int nf = 0; nf < 8; nf++)
                    mma_bf16(s[mf][nf], qa[mf][kc], kf[nf >> 1][nf & 1], kf[nf >> 1][(nf & 1) + 2]);
        }

        float mloc[4] = {-1e30f, -1e30f, -1e30f, -1e30f};
#pragma unroll
        for (int mf = 0; mf < 2; mf++)
#pragma unroll
            for (int nf = 0; nf < 8; nf++) {
                mloc[mf * 2 + 0] = fmaxf(mloc[mf * 2 + 0], fmaxf(s[mf][nf][0], s[mf][nf][1]));
                mloc[mf * 2 + 1] = fmaxf(mloc[mf * 2 + 1], fmaxf(s[mf][nf][2], s[mf][nf][3]));
            }
        float al[4];
#pragma unroll
        for (int j = 0; j < 4; j++) {
            mloc[j] = fmaxf(mloc[j], __shfl_xor_sync(0xffffffffu, mloc[j], 1));
            mloc[j] = fmaxf(mloc[j], __shfl_xor_sync(0xffffffffu, mloc[j], 2));
            float nm = fmaxf(rmax[j], mloc[j]);
            al[j] = __expf(rmax[j] - nm);
            rmax[j] = nm;
        }
        float l[4] = {};
        unsigned pa[2][4][4];
#pragma unroll
        for (int mf = 0; mf < 2; mf++)
#pragma unroll
            for (int nf = 0; nf < 8; nf++) {
                float p0 = __expf(s[mf][nf][0] - rmax[mf * 2 + 0]);
                float p1 = __expf(s[mf][nf][1] - rmax[mf * 2 + 0]);
                float p2 = __expf(s[mf][nf][2] - rmax[mf * 2 + 1]);
                float p3 = __expf(s[mf][nf][3] - rmax[mf * 2 + 1]);
                l[mf * 2 + 0] += p0 + p1;
                l[mf * 2 + 1] += p2 + p3;
                int kc = nf >> 1, off = (nf & 1) * 2;
                pa[mf][kc][off + 0] = packbf(p0, p1);
                pa[mf][kc][off + 1] = packbf(p2, p3);
            }
#pragma unroll
        for (int j = 0; j < 4; j++) {
            l[j] += __shfl_xor_sync(0xffffffffu, l[j], 1);
            l[j] += __shfl_xor_sync(0xffffffffu, l[j], 2);
            rsum[j] = rsum[j] * al[j] + l[j];
        }
#pragma unroll
        for (int mf = 0; mf < 2; mf++)
#pragma unroll
            for (int nf = 0; nf < 8; nf++) {
                o[mf][nf][0] *= al[mf * 2 + 0]; o[mf][nf][1] *= al[mf * 2 + 0];
                o[mf][nf][2] *= al[mf * 2 + 1]; o[mf][nf][3] *= al[mf * 2 + 1];
            }

#pragma unroll
        for (int kc = 0; kc < 4; kc++) {
            unsigned vf[4][4];
#pragma unroll
            for (int p = 0; p < 4; p++)
                ldsm4t(vf[p], sV + cur * KVSZ + ((kc * 16 + lrow) * LDS + p * 16 + lcol) * 2);
#pragma unroll
            for (int mf = 0; mf < 2; mf++)
#pragma unroll
                for (int nf = 0; nf < 8; nf++)
                    mma_bf16(o[mf][nf], pa[mf][kc],
                             vf[nf >> 1][(nf & 1) * 2], vf[nf >> 1][(nf & 1) * 2 + 1]);
        }

        __syncthreads();
        if (kt + 2 < NT) loadKV(kt + 2, cur);
        cp_commit();
    }

    float inv[4];
#pragma unroll
    for (int j = 0; j < 4; j++) inv[j] = 1.f / rsum[j];
#pragma unroll
    for (int mf = 0; mf < 2; mf++) {
        int row0 = qt * BQ + rr + mf * 16 + g;
        int row1 = row0 + 8;
#pragma unroll
        for (int nf = 0; nf < 8; nf++) {
            int cc = nf * 8 + 2 * tg;
            *reinterpret_cast<unsigned*>(ob + (size_t)row0 * DKK + cc) =
                packbf(o[mf][nf][0] * inv[mf * 2 + 0], o[mf][nf][1] * inv[mf * 2 + 0]);
            *reinterpret_cast<unsigned*>(ob + (size_t)row1 * DKK + cc) =
                packbf(o[mf][nf][2] * inv[mf * 2 + 1], o[mf][nf][3] * inv[mf * 2 + 1]);
        }
    }
}

// ---------------- LayerNorm ---------------------------------------------------
__global__ void __launch_bounds__(256) ln_kernel(const float* __restrict__ gamma,
                                                 const float* __restrict__ beta,
                                                 float* __restrict__ out) {
    __shared__ float red[16];
    const int row = blockIdx.x;
    const int tid = threadIdx.x;
    const float* xr = g_x + (size_t)row * DD;
    float4 xv = *reinterpret_cast<const float4*>(xr + tid * 4);
    float s = xv.x + xv.y + xv.z + xv.w;
    float q2 = xv.x * xv.x + xv.y * xv.y + xv.z * xv.z + xv.w * xv.w;
#pragma unroll
    for (int off = 16; off > 0; off >>= 1) {
        s += __shfl_xor_sync(0xffffffffu, s, off);
        q2 += __shfl_xor_sync(0xffffffffu, q2, off);
    }
    int warp = tid >> 5, lane = tid & 31;
    if (lane == 0) { red[warp] = s; red[8 + warp] = q2; }
    __syncthreads();
    if (tid < 32) {
        float ss = (tid < 8) ? red[tid] : 0.f;
        float qq = (tid < 8) ? red[8 + tid] : 0.f;
#pragma unroll
        for (int off = 4; off > 0; off >>= 1) {
            ss += __shfl_xor_sync(0xffffffffu, ss, off);
            qq += __shfl_xor_sync(0xffffffffu, qq, off);
        }
        if (tid == 0) { red[0] = ss; red[1] = qq; }
    }
    __syncthreads();
    float mean = red[0] * (1.f / (float)DD);
    float var = red[1] * (1.f / (float)DD) - mean * mean;
    float inv = rsqrtf(var + 1e-6f);
    int c = tid * 4;
    float4 gv = *reinterpret_cast<const float4*>(gamma + c);
    float4 bv = *reinterpret_cast<const float4*>(beta + c);
    float4 ov;
    ov.x = (xv.x - mean) * inv * gv.x + bv.x;
    ov.y = (xv.y - mean) * inv * gv.y + bv.y;
    ov.z = (xv.z - mean) * inv * gv.z + bv.z;
    ov.w = (xv.w - mean) * inv * gv.w + bv.w;
    *reinterpret_cast<float4*>(out + (size_t)row * DD + c) = ov;
}

// ---------------- launch ------------------------------------------------------
extern "C" void kernel_launch(void* const* d_in, const int* in_sizes, int n_in,
                              void* d_out, int out_size) {
    const float* q     = (const float*)d_in[0];
    const float* k     = (const float*)d_in[1];
    const float* v     = (const float*)d_in[2];
    const float* Wq    = (const float*)d_in[3];
    const float* bq    = (const float*)d_in[4];
    const float* Wk    = (const float*)d_in[5];
    const float* bk    = (const float*)d_in[6];
    const float* Wv    = (const float*)d_in[7];
    const float* bv    = (const float*)d_in[8];
    const float* Wo    = (const float*)d_in[9];
    const float* bo    = (const float*)d_in[10];
    const float* gamma = (const float*)d_in[11];
    const float* beta  = (const float*)d_in[12];
    float* out = (float*)d_out;

    cudaFuncSetAttribute(attn_kernel, cudaFuncAttributeMaxDynamicSharedMemorySize,
                         ATT_SMEM_BYTES);
    cudaFuncSetAttribute(qkv_kernel, cudaFuncAttributeMaxDynamicSharedMemorySize,
                         GEMM_SMEM);
    cudaFuncSetAttribute(oproj_kernel, cudaFuncAttributeMaxDynamicSharedMemorySize,
                         GEMM_SMEM);

    convert_kernel<<<28672, 256>>>(q, k, v, Wq, Wk, Wv, Wo);
    qkv_kernel<<<dim3(64, 8, 3), 256, GEMM_SMEM>>>(bq, bk, bv);
    attn_kernel<<<dim3(SS / BQ, BB * HH), 256, ATT_SMEM_BYTES>>>();
    oproj_kernel<<<dim3(64, 8), 256, GEMM_SMEM>>>(q, bo);
    ln_kernel<<<MROWS, 256>>>(gamma, beta, out);
}